// round 1
// baseline (speedup 1.0000x reference)
#include <cuda_runtime.h>

// ---------------------------------------------------------------------------
// GNN: L x { agg = scatter_add(h[src]*ew, dst); h = PReLU(LN(agg@Wrel + h@Wroot + b)) }
// then logits = LN(relu(h@W1+b1)) @ W2 + b2
// N=100000, E=1600000, D=H=128, L=3, C=2 (sizes taken from in_sizes at launch)
// ---------------------------------------------------------------------------

#define MAXN 100000
#define DD   128

// Scratch (no allocations allowed): ping-pong node features + aggregation buffer.
__device__ float g_buf0[MAXN * DD];
__device__ float g_buf1[MAXN * DD];
__device__ float g_agg [MAXN * DD];

// ---------------------------------------------------------------------------
// Scatter: one warp per edge. Gather h[src] (float4/lane), scale by edge weight,
// vector-reduce-add into agg[dst]. red.global.add.v4.f32 = no-return L2 atomic.
// ---------------------------------------------------------------------------
__global__ void scatter_kernel(const float* __restrict__ h,
                               const int*   __restrict__ ei,
                               const float* __restrict__ ew,
                               float*       __restrict__ agg,
                               int E) {
    int wid  = (blockIdx.x * blockDim.x + threadIdx.x) >> 5;
    int lane = threadIdx.x & 31;
    if (wid >= E) return;
    int   src = __ldg(ei + wid);
    int   dst = __ldg(ei + E + wid);
    float w   = __ldg(ew + wid);
    float4 v = *reinterpret_cast<const float4*>(h + (size_t)src * DD + lane * 4);
    v.x *= w; v.y *= w; v.z *= w; v.w *= w;
    float* ap = agg + (size_t)dst * DD + lane * 4;
    asm volatile("red.global.add.v4.f32 [%0], {%1,%2,%3,%4};"
                 :: "l"(ap), "f"(v.x), "f"(v.y), "f"(v.z), "f"(v.w)
                 : "memory");
}

// ---------------------------------------------------------------------------
// Fused dual-GEMM + bias + LayerNorm + PReLU. One warp per node row; both
// 128x128 weight matrices live in SMEM (loaded once per persistent block).
// Lane l owns output columns 4l..4l+3.
// ---------------------------------------------------------------------------
__global__ __launch_bounds__(512, 1)
void gemm_ln_prelu(const float* __restrict__ hin,
                   const float* __restrict__ agg,
                   const float* __restrict__ Wrel,
                   const float* __restrict__ Wroot,
                   const float* __restrict__ bias,
                   const float* __restrict__ lng,
                   const float* __restrict__ lnb,
                   const float* __restrict__ alpha,
                   float*       __restrict__ hout,
                   int N) {
    extern __shared__ float smem[];
    float4* sWr   = reinterpret_cast<float4*>(smem);            // 4096 float4 (64KB)
    float4* sWo   = reinterpret_cast<float4*>(smem + 16384);    // 4096 float4 (64KB)
    float*  sRows = smem + 32768;                               // 16 warps * 256 floats

    int tid = threadIdx.x;
    int lane = tid & 31, warp = tid >> 5;

    const float4* Wr4 = reinterpret_cast<const float4*>(Wrel);
    const float4* Wo4 = reinterpret_cast<const float4*>(Wroot);
    #pragma unroll
    for (int i = tid; i < 4096; i += 512) { sWr[i] = Wr4[i]; sWo[i] = Wo4[i]; }
    __syncthreads();

    float  al  = __ldg(alpha);
    float4 biv = *reinterpret_cast<const float4*>(bias + lane * 4);
    float4 gg  = *reinterpret_cast<const float4*>(lng  + lane * 4);
    float4 bb  = *reinterpret_cast<const float4*>(lnb  + lane * 4);

    float* sa = sRows + warp * 256;  // [0..127]=agg row, [128..255]=h row

    for (int row = blockIdx.x * 16 + warp; row < N; row += gridDim.x * 16) {
        float4 a = *reinterpret_cast<const float4*>(agg + (size_t)row * DD + lane * 4);
        float4 x = *reinterpret_cast<const float4*>(hin + (size_t)row * DD + lane * 4);
        reinterpret_cast<float4*>(sa)[lane]       = a;
        reinterpret_cast<float4*>(sa + 128)[lane] = x;
        __syncwarp();

        float4 acc = biv;
        #pragma unroll 16
        for (int k = 0; k < 128; k++) {
            float  ak = sa[k];
            float  xk = sa[128 + k];
            float4 wr = sWr[k * 32 + lane];
            float4 wo = sWo[k * 32 + lane];
            acc.x = fmaf(ak, wr.x, fmaf(xk, wo.x, acc.x));
            acc.y = fmaf(ak, wr.y, fmaf(xk, wo.y, acc.y));
            acc.z = fmaf(ak, wr.z, fmaf(xk, wo.z, acc.z));
            acc.w = fmaf(ak, wr.w, fmaf(xk, wo.w, acc.w));
        }
        __syncwarp();

        // LayerNorm over the 128 columns held across the warp (4/lane)
        float s = acc.x + acc.y + acc.z + acc.w;
        #pragma unroll
        for (int o = 16; o; o >>= 1) s += __shfl_xor_sync(0xffffffffu, s, o);
        float mu = s * 0.0078125f;
        float dx = acc.x - mu, dy = acc.y - mu, dz = acc.z - mu, dw = acc.w - mu;
        float q = dx * dx + dy * dy + dz * dz + dw * dw;
        #pragma unroll
        for (int o = 16; o; o >>= 1) q += __shfl_xor_sync(0xffffffffu, q, o);
        float rstd = rsqrtf(q * 0.0078125f + 1e-5f);

        float4 y;
        y.x = dx * rstd * gg.x + bb.x;
        y.y = dy * rstd * gg.y + bb.y;
        y.z = dz * rstd * gg.z + bb.z;
        y.w = dw * rstd * gg.w + bb.w;
        y.x = y.x >= 0.f ? y.x : al * y.x;
        y.y = y.y >= 0.f ? y.y : al * y.y;
        y.z = y.z >= 0.f ? y.z : al * y.z;
        y.w = y.w >= 0.f ? y.w : al * y.w;

        *reinterpret_cast<float4*>(hout + (size_t)row * DD + lane * 4) = y;
    }
}

// ---------------------------------------------------------------------------
// Classifier: logits = LN(relu(h@W1 + b1)) @ W2 + b2, one warp per row.
// ---------------------------------------------------------------------------
__global__ __launch_bounds__(512, 2)
void classifier_kernel(const float* __restrict__ hin,
                       const float* __restrict__ W1,
                       const float* __restrict__ b1,
                       const float* __restrict__ lng,
                       const float* __restrict__ lnb,
                       const float* __restrict__ W2,
                       const float* __restrict__ b2,
                       float*       __restrict__ out,
                       int N) {
    extern __shared__ float smem[];
    float4* sW1   = reinterpret_cast<float4*>(smem);          // 4096 float4 (64KB)
    float*  sRows = smem + 16384;                              // 16 warps * 128

    int tid = threadIdx.x;
    int lane = tid & 31, warp = tid >> 5;

    const float4* W14 = reinterpret_cast<const float4*>(W1);
    #pragma unroll
    for (int i = tid; i < 4096; i += 512) sW1[i] = W14[i];
    __syncthreads();

    float4 b1v = *reinterpret_cast<const float4*>(b1  + lane * 4);
    float4 gg  = *reinterpret_cast<const float4*>(lng + lane * 4);
    float4 bb  = *reinterpret_cast<const float4*>(lnb + lane * 4);
    // W2 [128,2]: lane l holds rows 4l..4l+3 for both output columns
    float w2c0x = __ldg(W2 + (lane * 4 + 0) * 2 + 0);
    float w2c0y = __ldg(W2 + (lane * 4 + 1) * 2 + 0);
    float w2c0z = __ldg(W2 + (lane * 4 + 2) * 2 + 0);
    float w2c0w = __ldg(W2 + (lane * 4 + 3) * 2 + 0);
    float w2c1x = __ldg(W2 + (lane * 4 + 0) * 2 + 1);
    float w2c1y = __ldg(W2 + (lane * 4 + 1) * 2 + 1);
    float w2c1z = __ldg(W2 + (lane * 4 + 2) * 2 + 1);
    float w2c1w = __ldg(W2 + (lane * 4 + 3) * 2 + 1);
    float b20 = __ldg(b2 + 0), b21 = __ldg(b2 + 1);

    float* sx = sRows + warp * 128;

    for (int row = blockIdx.x * 16 + warp; row < N; row += gridDim.x * 16) {
        float4 x = *reinterpret_cast<const float4*>(hin + (size_t)row * DD + lane * 4);
        reinterpret_cast<float4*>(sx)[lane] = x;
        __syncwarp();

        float4 acc = b1v;
        #pragma unroll 16
        for (int k = 0; k < 128; k++) {
            float  xk = sx[k];
            float4 w  = sW1[k * 32 + lane];
            acc.x = fmaf(xk, w.x, acc.x);
            acc.y = fmaf(xk, w.y, acc.y);
            acc.z = fmaf(xk, w.z, acc.z);
            acc.w = fmaf(xk, w.w, acc.w);
        }
        __syncwarp();

        // ReLU
        acc.x = fmaxf(acc.x, 0.f); acc.y = fmaxf(acc.y, 0.f);
        acc.z = fmaxf(acc.z, 0.f); acc.w = fmaxf(acc.w, 0.f);

        // LayerNorm
        float s = acc.x + acc.y + acc.z + acc.w;
        #pragma unroll
        for (int o = 16; o; o >>= 1) s += __shfl_xor_sync(0xffffffffu, s, o);
        float mu = s * 0.0078125f;
        float dx = acc.x - mu, dy = acc.y - mu, dz = acc.z - mu, dw = acc.w - mu;
        float q = dx * dx + dy * dy + dz * dz + dw * dw;
        #pragma unroll
        for (int o = 16; o; o >>= 1) q += __shfl_xor_sync(0xffffffffu, q, o);
        float rstd = rsqrtf(q * 0.0078125f + 1e-5f);
        float zx = dx * rstd * gg.x + bb.x;
        float zy = dy * rstd * gg.y + bb.y;
        float zz = dz * rstd * gg.z + bb.z;
        float zw = dw * rstd * gg.w + bb.w;

        // logits = z @ W2 + b2 (warp reduction of per-lane partials)
        float p0 = zx * w2c0x + zy * w2c0y + zz * w2c0z + zw * w2c0w;
        float p1 = zx * w2c1x + zy * w2c1y + zz * w2c1z + zw * w2c1w;
        #pragma unroll
        for (int o = 16; o; o >>= 1) {
            p0 += __shfl_xor_sync(0xffffffffu, p0, o);
            p1 += __shfl_xor_sync(0xffffffffu, p1, o);
        }
        if (lane == 0) {
            out[(size_t)row * 2 + 0] = p0 + b20;
            out[(size_t)row * 2 + 1] = p1 + b21;
        }
    }
}

// ---------------------------------------------------------------------------
extern "C" void kernel_launch(void* const* d_in, const int* in_sizes, int n_in,
                              void* d_out, int out_size) {
    const float* features = (const float*)d_in[0];
    const int*   ei       = (const int*)  d_in[1];
    const float* ew       = (const float*)d_in[2];
    const float* Wrel     = (const float*)d_in[3];
    const float* Wroot    = (const float*)d_in[4];
    const float* bias     = (const float*)d_in[5];
    const float* lng      = (const float*)d_in[6];
    const float* lnb      = (const float*)d_in[7];
    const float* alpha    = (const float*)d_in[8];
    const float* W1       = (const float*)d_in[9];
    const float* b1       = (const float*)d_in[10];
    const float* cg       = (const float*)d_in[11];
    const float* cb       = (const float*)d_in[12];
    const float* W2       = (const float*)d_in[13];
    const float* b2       = (const float*)d_in[14];

    int N = in_sizes[0] / DD;
    int E = in_sizes[1] / 2;
    int L = in_sizes[8];

    float *buf0, *buf1, *agg;
    cudaGetSymbolAddress((void**)&buf0, g_buf0);
    cudaGetSymbolAddress((void**)&buf1, g_buf1);
    cudaGetSymbolAddress((void**)&agg,  g_agg);

    int sm = 148;
    cudaDeviceGetAttribute(&sm, cudaDevAttrMultiProcessorCount, 0);

    size_t smemG = (size_t)(32768 + 16 * 256) * sizeof(float);   // 144 KB
    size_t smemC = (size_t)(16384 + 16 * 128) * sizeof(float);   //  72 KB
    cudaFuncSetAttribute(gemm_ln_prelu,     cudaFuncAttributeMaxDynamicSharedMemorySize, (int)smemG);
    cudaFuncSetAttribute(classifier_kernel, cudaFuncAttributeMaxDynamicSharedMemorySize, (int)smemC);

    int scatterBlocks = (E + 7) / 8;  // 8 warps (edges) per 256-thread block

    const float* hin = features;
    float* pong[2] = { buf0, buf1 };
    for (int i = 0; i < L; i++) {
        float* hout = pong[i & 1];
        cudaMemsetAsync(agg, 0, (size_t)N * DD * sizeof(float));
        scatter_kernel<<<scatterBlocks, 256>>>(hin, ei, ew, agg, E);
        gemm_ln_prelu<<<sm, 512, smemG>>>(hin, agg,
                                          Wrel  + (size_t)i * DD * DD,
                                          Wroot + (size_t)i * DD * DD,
                                          bias + i * DD, lng + i * DD, lnb + i * DD,
                                          alpha + i, hout, N);
        hin = hout;
    }
    classifier_kernel<<<2 * sm, 512, smemC>>>(hin, W1, b1, cg, cb, W2, b2,
                                              (float*)d_out, N);
}

// round 2
// speedup vs baseline: 2.8138x; 2.8138x over previous
#include <cuda_runtime.h>

// ---------------------------------------------------------------------------
// GNN: L x { agg = scatter_add(h[src]*ew, dst); h = PReLU(LN(agg@Wrel + h@Wroot + b)) }
// then logits = LN(relu(h@W1+b1)) @ W2 + b2
// ---------------------------------------------------------------------------

#define MAXN 100000
#define DD   128
typedef unsigned long long U64;

__device__ float g_buf0[MAXN * DD];
__device__ float g_buf1[MAXN * DD];
__device__ float g_agg [MAXN * DD];

// ---- packed f32x2 helpers (FFMA2 path: 2x fp32 FMA throughput on sm_103a) ----
__device__ __forceinline__ U64 pk2(float lo, float hi) {
    U64 r; asm("mov.b64 %0,{%1,%2};" : "=l"(r) : "f"(lo), "f"(hi)); return r;
}
__device__ __forceinline__ void upk2(U64 v, float& lo, float& hi) {
    asm("mov.b64 {%0,%1},%2;" : "=f"(lo), "=f"(hi) : "l"(v));
}
__device__ __forceinline__ U64 f2(U64 a, U64 b, U64 c) {
    asm("fma.rn.f32x2 %0,%1,%2,%0;" : "+l"(c) : "l"(a), "l"(b)); return c;
}
__device__ __forceinline__ U64 add2(U64 a, U64 b) {
    U64 r; asm("add.rn.f32x2 %0,%1,%2;" : "=l"(r) : "l"(a), "l"(b)); return r;
}
__device__ __forceinline__ U64 mul2(U64 a, U64 b) {
    U64 r; asm("mul.rn.f32x2 %0,%1,%2;" : "=l"(r) : "l"(a), "l"(b)); return r;
}
__device__ __forceinline__ U64 shfl64(U64 v, int o) {
    return (U64)__shfl_xor_sync(0xffffffffu, (long long)v, o);
}

// ---------------------------------------------------------------------------
// Scatter: one warp per edge, red.global.add.v4.f32 (no-return L2 reduction).
// ---------------------------------------------------------------------------
__global__ void scatter_kernel(const float* __restrict__ h,
                               const int*   __restrict__ ei,
                               const float* __restrict__ ew,
                               float*       __restrict__ agg,
                               int E) {
    int wid  = (blockIdx.x * blockDim.x + threadIdx.x) >> 5;
    int lane = threadIdx.x & 31;
    if (wid >= E) return;
    int   src = __ldg(ei + wid);
    int   dst = __ldg(ei + E + wid);
    float w   = __ldg(ew + wid);
    float4 v = *reinterpret_cast<const float4*>(h + (size_t)src * DD + lane * 4);
    v.x *= w; v.y *= w; v.z *= w; v.w *= w;
    float* ap = agg + (size_t)dst * DD + lane * 4;
    asm volatile("red.global.add.v4.f32 [%0], {%1,%2,%3,%4};"
                 :: "l"(ap), "f"(v.x), "f"(v.y), "f"(v.z), "f"(v.w)
                 : "memory");
}

// ---------------------------------------------------------------------------
// Fused dual-GEMM + bias + LN + PReLU.
// 256 threads (8 warps), each warp computes 8 rows (4 row-pairs packed in
// f32x2). Weights (2x64KB) in SMEM; row values staged interleaved as
// {row_even[k], row_odd[k]} u64 pairs so the FFMA2 'a' operand loads packed.
// ---------------------------------------------------------------------------
__global__ __launch_bounds__(256, 1)
void gemm_ln_prelu(const float* __restrict__ hin,
                   const float* __restrict__ agg,
                   const float* __restrict__ Wrel,
                   const float* __restrict__ Wroot,
                   const float* __restrict__ bias,
                   const float* __restrict__ lng,
                   const float* __restrict__ lnb,
                   const float* __restrict__ alpha,
                   float*       __restrict__ hout,
                   int N) {
    extern __shared__ float smem[];
    float4* sWr4 = reinterpret_cast<float4*>(smem);             // 64 KB
    float4* sWo4 = reinterpret_cast<float4*>(smem + 16384);     // 64 KB
    U64*    sP   = reinterpret_cast<U64*>(smem + 32768);        // 64 KB staging

    int tid = threadIdx.x, lane = tid & 31, warp = tid >> 5;

    const float4* Wr4 = reinterpret_cast<const float4*>(Wrel);
    const float4* Wo4 = reinterpret_cast<const float4*>(Wroot);
    #pragma unroll
    for (int i = tid; i < 4096; i += 256) { sWr4[i] = Wr4[i]; sWo4[i] = Wo4[i]; }
    __syncthreads();

    float  al  = __ldg(alpha);
    float4 biv = *reinterpret_cast<const float4*>(bias + lane * 4);
    float4 gg  = *reinterpret_cast<const float4*>(lng  + lane * 4);
    float4 bb  = *reinterpret_cast<const float4*>(lnb  + lane * 4);
    float gA[4] = {gg.x, gg.y, gg.z, gg.w};
    float bA[4] = {bb.x, bb.y, bb.z, bb.w};
    U64 bp[4] = {pk2(biv.x, biv.x), pk2(biv.y, biv.y),
                 pk2(biv.z, biv.z), pk2(biv.w, biv.w)};
    const U64 NEG1   = pk2(-1.f, -1.f);
    const U64 INV128 = pk2(0.0078125f, 0.0078125f);

    U64* sw = sP + warp * 1024;   // 4 pairs x 2 mats x 128 u64
    int gw = blockIdx.x * 8 + warp;
    int stride = gridDim.x * 8 * 8;

    for (int base = gw * 8; base < N; base += stride) {
        __syncwarp();
        // -------- stage 8 rows interleaved as row-pairs --------
        #pragma unroll
        for (int p = 0; p < 4; p++) {
            int r0 = base + 2 * p, r1 = r0 + 1;
            float4 a0 = {0,0,0,0}, a1 = {0,0,0,0}, h0 = {0,0,0,0}, h1 = {0,0,0,0};
            if (r0 < N) {
                a0 = *reinterpret_cast<const float4*>(agg + (size_t)r0 * DD + lane * 4);
                h0 = *reinterpret_cast<const float4*>(hin + (size_t)r0 * DD + lane * 4);
            }
            if (r1 < N) {
                a1 = *reinterpret_cast<const float4*>(agg + (size_t)r1 * DD + lane * 4);
                h1 = *reinterpret_cast<const float4*>(hin + (size_t)r1 * DD + lane * 4);
            }
            float2* da = reinterpret_cast<float2*>(sw + (2 * p) * 128);
            float2* dh = reinterpret_cast<float2*>(sw + (2 * p + 1) * 128);
            da[lane * 4 + 0] = make_float2(a0.x, a1.x);
            da[lane * 4 + 1] = make_float2(a0.y, a1.y);
            da[lane * 4 + 2] = make_float2(a0.z, a1.z);
            da[lane * 4 + 3] = make_float2(a0.w, a1.w);
            dh[lane * 4 + 0] = make_float2(h0.x, h1.x);
            dh[lane * 4 + 1] = make_float2(h0.y, h1.y);
            dh[lane * 4 + 2] = make_float2(h0.z, h1.z);
            dh[lane * 4 + 3] = make_float2(h0.w, h1.w);
        }
        __syncwarp();

        // -------- main K loop --------
        U64 acc[4][4];
        #pragma unroll
        for (int p = 0; p < 4; p++)
            #pragma unroll
            for (int c = 0; c < 4; c++) acc[p][c] = bp[c];

        #pragma unroll 4
        for (int k = 0; k < 128; k += 2) {
            float4 wr0 = sWr4[k * 32 + lane],      wr1 = sWr4[k * 32 + 32 + lane];
            float4 wo0 = sWo4[k * 32 + lane],      wo1 = sWo4[k * 32 + 32 + lane];
            U64 wr0p[4] = {pk2(wr0.x,wr0.x), pk2(wr0.y,wr0.y), pk2(wr0.z,wr0.z), pk2(wr0.w,wr0.w)};
            U64 wr1p[4] = {pk2(wr1.x,wr1.x), pk2(wr1.y,wr1.y), pk2(wr1.z,wr1.z), pk2(wr1.w,wr1.w)};
            U64 wo0p[4] = {pk2(wo0.x,wo0.x), pk2(wo0.y,wo0.y), pk2(wo0.z,wo0.z), pk2(wo0.w,wo0.w)};
            U64 wo1p[4] = {pk2(wo1.x,wo1.x), pk2(wo1.y,wo1.y), pk2(wo1.z,wo1.z), pk2(wo1.w,wo1.w)};
            #pragma unroll
            for (int p = 0; p < 4; p++) {
                ulonglong2 ap = *reinterpret_cast<const ulonglong2*>(sw + (2 * p) * 128 + k);
                ulonglong2 hp = *reinterpret_cast<const ulonglong2*>(sw + (2 * p + 1) * 128 + k);
                #pragma unroll
                for (int c = 0; c < 4; c++) {
                    acc[p][c] = f2(ap.x, wr0p[c], acc[p][c]);
                    acc[p][c] = f2(hp.x, wo0p[c], acc[p][c]);
                    acc[p][c] = f2(ap.y, wr1p[c], acc[p][c]);
                    acc[p][c] = f2(hp.y, wo1p[c], acc[p][c]);
                }
            }
        }

        // -------- epilogue: LayerNorm + PReLU (two rows per pair) --------
        #pragma unroll
        for (int p = 0; p < 4; p++) {
            U64 s = add2(add2(acc[p][0], acc[p][1]), add2(acc[p][2], acc[p][3]));
            #pragma unroll
            for (int o = 16; o; o >>= 1) s = add2(s, shfl64(s, o));
            U64 mu = mul2(s, INV128);
            U64 d[4];
            #pragma unroll
            for (int c = 0; c < 4; c++) d[c] = f2(mu, NEG1, acc[p][c]);
            U64 q = add2(add2(mul2(d[0], d[0]), mul2(d[1], d[1])),
                         add2(mul2(d[2], d[2]), mul2(d[3], d[3])));
            #pragma unroll
            for (int o = 16; o; o >>= 1) q = add2(q, shfl64(q, o));
            float ql, qh; upk2(q, ql, qh);
            float rl = rsqrtf(ql * 0.0078125f + 1e-5f);
            float rh = rsqrtf(qh * 0.0078125f + 1e-5f);

            int r0 = base + 2 * p, r1 = r0 + 1;
            float y0[4], y1[4];
            #pragma unroll
            for (int c = 0; c < 4; c++) {
                float dl, dh2; upk2(d[c], dl, dh2);
                float v0 = dl * rl * gA[c] + bA[c];
                float v1 = dh2 * rh * gA[c] + bA[c];
                y0[c] = v0 >= 0.f ? v0 : al * v0;
                y1[c] = v1 >= 0.f ? v1 : al * v1;
            }
            if (r0 < N)
                *reinterpret_cast<float4*>(hout + (size_t)r0 * DD + lane * 4) =
                    make_float4(y0[0], y0[1], y0[2], y0[3]);
            if (r1 < N)
                *reinterpret_cast<float4*>(hout + (size_t)r1 * DD + lane * 4) =
                    make_float4(y1[0], y1[1], y1[2], y1[3]);
        }
    }
}

// ---------------------------------------------------------------------------
// Classifier: logits = LN(relu(h@W1+b1)) @ W2 + b2. Same 8-rows/warp FFMA2
// scheme, single weight matrix (96 KB smem -> 2 blocks/SM).
// ---------------------------------------------------------------------------
__global__ __launch_bounds__(256, 2)
void classifier_kernel(const float* __restrict__ hin,
                       const float* __restrict__ W1,
                       const float* __restrict__ b1,
                       const float* __restrict__ lng,
                       const float* __restrict__ lnb,
                       const float* __restrict__ W2,
                       const float* __restrict__ b2,
                       float*       __restrict__ out,
                       int N) {
    extern __shared__ float smem[];
    float4* sW4 = reinterpret_cast<float4*>(smem);          // 64 KB
    U64*    sP  = reinterpret_cast<U64*>(smem + 16384);     // 32 KB staging

    int tid = threadIdx.x, lane = tid & 31, warp = tid >> 5;

    const float4* W14 = reinterpret_cast<const float4*>(W1);
    #pragma unroll
    for (int i = tid; i < 4096; i += 256) sW4[i] = W14[i];
    __syncthreads();

    float4 b1v = *reinterpret_cast<const float4*>(b1  + lane * 4);
    float4 gg  = *reinterpret_cast<const float4*>(lng + lane * 4);
    float4 bb  = *reinterpret_cast<const float4*>(lnb + lane * 4);
    float gA[4] = {gg.x, gg.y, gg.z, gg.w};
    float bA[4] = {bb.x, bb.y, bb.z, bb.w};
    U64 bp[4] = {pk2(b1v.x, b1v.x), pk2(b1v.y, b1v.y),
                 pk2(b1v.z, b1v.z), pk2(b1v.w, b1v.w)};
    const U64 NEG1   = pk2(-1.f, -1.f);
    const U64 INV128 = pk2(0.0078125f, 0.0078125f);

    float w2c0[4], w2c1[4];
    #pragma unroll
    for (int c = 0; c < 4; c++) {
        w2c0[c] = __ldg(W2 + (lane * 4 + c) * 2 + 0);
        w2c1[c] = __ldg(W2 + (lane * 4 + c) * 2 + 1);
    }
    float b20 = __ldg(b2 + 0), b21 = __ldg(b2 + 1);

    U64* sw = sP + warp * 512;   // 4 pairs x 128 u64
    int gw = blockIdx.x * 8 + warp;
    int stride = gridDim.x * 8 * 8;

    for (int base = gw * 8; base < N; base += stride) {
        __syncwarp();
        #pragma unroll
        for (int p = 0; p < 4; p++) {
            int r0 = base + 2 * p, r1 = r0 + 1;
            float4 x0 = {0,0,0,0}, x1 = {0,0,0,0};
            if (r0 < N) x0 = *reinterpret_cast<const float4*>(hin + (size_t)r0 * DD + lane * 4);
            if (r1 < N) x1 = *reinterpret_cast<const float4*>(hin + (size_t)r1 * DD + lane * 4);
            float2* dx = reinterpret_cast<float2*>(sw + p * 128);
            dx[lane * 4 + 0] = make_float2(x0.x, x1.x);
            dx[lane * 4 + 1] = make_float2(x0.y, x1.y);
            dx[lane * 4 + 2] = make_float2(x0.z, x1.z);
            dx[lane * 4 + 3] = make_float2(x0.w, x1.w);
        }
        __syncwarp();

        U64 acc[4][4];
        #pragma unroll
        for (int p = 0; p < 4; p++)
            #pragma unroll
            for (int c = 0; c < 4; c++) acc[p][c] = bp[c];

        #pragma unroll 4
        for (int k = 0; k < 128; k += 2) {
            float4 w0 = sW4[k * 32 + lane], w1 = sW4[k * 32 + 32 + lane];
            U64 w0p[4] = {pk2(w0.x,w0.x), pk2(w0.y,w0.y), pk2(w0.z,w0.z), pk2(w0.w,w0.w)};
            U64 w1p[4] = {pk2(w1.x,w1.x), pk2(w1.y,w1.y), pk2(w1.z,w1.z), pk2(w1.w,w1.w)};
            #pragma unroll
            for (int p = 0; p < 4; p++) {
                ulonglong2 xp = *reinterpret_cast<const ulonglong2*>(sw + p * 128 + k);
                #pragma unroll
                for (int c = 0; c < 4; c++) {
                    acc[p][c] = f2(xp.x, w0p[c], acc[p][c]);
                    acc[p][c] = f2(xp.y, w1p[c], acc[p][c]);
                }
            }
        }

        #pragma unroll
        for (int p = 0; p < 4; p++) {
            // ReLU both halves
            #pragma unroll
            for (int c = 0; c < 4; c++) {
                float lo, hi; upk2(acc[p][c], lo, hi);
                acc[p][c] = pk2(fmaxf(lo, 0.f), fmaxf(hi, 0.f));
            }
            U64 s = add2(add2(acc[p][0], acc[p][1]), add2(acc[p][2], acc[p][3]));
            #pragma unroll
            for (int o = 16; o; o >>= 1) s = add2(s, shfl64(s, o));
            U64 mu = mul2(s, INV128);
            U64 d[4];
            #pragma unroll
            for (int c = 0; c < 4; c++) d[c] = f2(mu, NEG1, acc[p][c]);
            U64 q = add2(add2(mul2(d[0], d[0]), mul2(d[1], d[1])),
                         add2(mul2(d[2], d[2]), mul2(d[3], d[3])));
            #pragma unroll
            for (int o = 16; o; o >>= 1) q = add2(q, shfl64(q, o));
            float ql, qh; upk2(q, ql, qh);
            float rl = rsqrtf(ql * 0.0078125f + 1e-5f);
            float rh = rsqrtf(qh * 0.0078125f + 1e-5f);

            float p0lo = 0.f, p1lo = 0.f, p0hi = 0.f, p1hi = 0.f;
            #pragma unroll
            for (int c = 0; c < 4; c++) {
                float dl, dh2; upk2(d[c], dl, dh2);
                float zl = dl * rl * gA[c] + bA[c];
                float zh = dh2 * rh * gA[c] + bA[c];
                p0lo += zl * w2c0[c]; p1lo += zl * w2c1[c];
                p0hi += zh * w2c0[c]; p1hi += zh * w2c1[c];
            }
            U64 P0 = pk2(p0lo, p0hi), P1 = pk2(p1lo, p1hi);
            #pragma unroll
            for (int o = 16; o; o >>= 1) {
                P0 = add2(P0, shfl64(P0, o));
                P1 = add2(P1, shfl64(P1, o));
            }
            if (lane == 0) {
                float a0, a1, c0, c1;
                upk2(P0, a0, a1); upk2(P1, c0, c1);
                int r0 = base + 2 * p, r1 = r0 + 1;
                if (r0 < N) { out[(size_t)r0 * 2 + 0] = a0 + b20; out[(size_t)r0 * 2 + 1] = c0 + b21; }
                if (r1 < N) { out[(size_t)r1 * 2 + 0] = a1 + b20; out[(size_t)r1 * 2 + 1] = c1 + b21; }
            }
        }
    }
}

// ---------------------------------------------------------------------------
extern "C" void kernel_launch(void* const* d_in, const int* in_sizes, int n_in,
                              void* d_out, int out_size) {
    const float* features = (const float*)d_in[0];
    const int*   ei       = (const int*)  d_in[1];
    const float* ew       = (const float*)d_in[2];
    const float* Wrel     = (const float*)d_in[3];
    const float* Wroot    = (const float*)d_in[4];
    const float* bias     = (const float*)d_in[5];
    const float* lng      = (const float*)d_in[6];
    const float* lnb      = (const float*)d_in[7];
    const float* alpha    = (const float*)d_in[8];
    const float* W1       = (const float*)d_in[9];
    const float* b1       = (const float*)d_in[10];
    const float* cg       = (const float*)d_in[11];
    const float* cb       = (const float*)d_in[12];
    const float* W2       = (const float*)d_in[13];
    const float* b2       = (const float*)d_in[14];

    int N = in_sizes[0] / DD;
    int E = in_sizes[1] / 2;
    int L = in_sizes[8];

    float *buf0, *buf1, *agg;
    cudaGetSymbolAddress((void**)&buf0, g_buf0);
    cudaGetSymbolAddress((void**)&buf1, g_buf1);
    cudaGetSymbolAddress((void**)&agg,  g_agg);

    int sm = 148;
    cudaDeviceGetAttribute(&sm, cudaDevAttrMultiProcessorCount, 0);

    size_t smemG = 196608;  // 64+64+64 KB
    size_t smemC = 98304;   // 64+32 KB
    cudaFuncSetAttribute(gemm_ln_prelu,     cudaFuncAttributeMaxDynamicSharedMemorySize, (int)smemG);
    cudaFuncSetAttribute(classifier_kernel, cudaFuncAttributeMaxDynamicSharedMemorySize, (int)smemC);

    int scatterBlocks = (E + 7) / 8;

    const float* hin = features;
    float* pong[2] = { buf0, buf1 };
    for (int i = 0; i < L; i++) {
        float* hout = pong[i & 1];
        cudaMemsetAsync(agg, 0, (size_t)N * DD * sizeof(float));
        scatter_kernel<<<scatterBlocks, 256>>>(hin, ei, ew, agg, E);
        gemm_ln_prelu<<<sm, 256, smemG>>>(hin, agg,
                                          Wrel  + (size_t)i * DD * DD,
                                          Wroot + (size_t)i * DD * DD,
                                          bias + i * DD, lng + i * DD, lnb + i * DD,
                                          alpha + i, hout, N);
        hin = hout;
    }
    classifier_kernel<<<2 * sm, 256, smemC>>>(hin, W1, b1, cg, cb, W2, b2,
                                              (float*)d_out, N);
}

// round 3
// speedup vs baseline: 4.3135x; 1.5330x over previous
#include <cuda_runtime.h>

// ---------------------------------------------------------------------------
// GNN: L x { agg = scatter_add(h[src]*ew, dst); h = PReLU(LN(agg@Wrel + h@Wroot + b)) }
// then logits = LN(relu(h@W1+b1)) @ W2 + b2
// R3: CSR-by-destination built once per call (no atomics in the hot loop),
//     gemm at 12 warps for latency hiding.
// ---------------------------------------------------------------------------

#define MAXN 100000
#define MAXE 1600000
#define DD   128
typedef unsigned long long U64;

__device__ float g_buf0[MAXN * DD];
__device__ float g_buf1[MAXN * DD];
__device__ float g_agg [MAXN * DD];
__device__ int   g_cnt [MAXN];        // histogram, then reused as cursor
__device__ int   g_off [MAXN + 1];
__device__ int   g_bsum[128];
__device__ int   g_esrc[MAXE];
__device__ float g_ewt [MAXE];

// ---- packed f32x2 helpers ----
__device__ __forceinline__ U64 pk2(float lo, float hi) {
    U64 r; asm("mov.b64 %0,{%1,%2};" : "=l"(r) : "f"(lo), "f"(hi)); return r;
}
__device__ __forceinline__ void upk2(U64 v, float& lo, float& hi) {
    asm("mov.b64 {%0,%1},%2;" : "=f"(lo), "=f"(hi) : "l"(v));
}
__device__ __forceinline__ U64 f2(U64 a, U64 b, U64 c) {
    asm("fma.rn.f32x2 %0,%1,%2,%0;" : "+l"(c) : "l"(a), "l"(b)); return c;
}
__device__ __forceinline__ U64 add2(U64 a, U64 b) {
    U64 r; asm("add.rn.f32x2 %0,%1,%2;" : "=l"(r) : "l"(a), "l"(b)); return r;
}
__device__ __forceinline__ U64 mul2(U64 a, U64 b) {
    U64 r; asm("mul.rn.f32x2 %0,%1,%2;" : "=l"(r) : "l"(a), "l"(b)); return r;
}
__device__ __forceinline__ U64 shfl64(U64 v, int o) {
    return (U64)__shfl_xor_sync(0xffffffffu, (long long)v, o);
}

// ======================= CSR build (once per call) =========================
__global__ void hist_kernel(const int* __restrict__ ei, int* __restrict__ cnt, int E) {
    int e = blockIdx.x * blockDim.x + threadIdx.x;
    if (e < E) atomicAdd(cnt + __ldg(ei + E + e), 1);
}

// block-local exclusive scan (1024 elements per block)
__global__ void scan1_kernel(const int* __restrict__ cnt, int* __restrict__ off,
                             int* __restrict__ bsum, int N) {
    __shared__ int s[1024];
    int tid = threadIdx.x;
    int i = blockIdx.x * 1024 + tid;
    int v = (i < N) ? cnt[i] : 0;
    s[tid] = v; __syncthreads();
    #pragma unroll
    for (int d = 1; d < 1024; d <<= 1) {
        int t = (tid >= d) ? s[tid - d] : 0;
        __syncthreads();
        s[tid] += t;
        __syncthreads();
    }
    if (i < N) off[i] = s[tid] - v;          // exclusive within block
    if (tid == 1023) bsum[blockIdx.x] = s[1023];
}

// scan of block sums (<=128 blocks), writes off[N] = total
__global__ void scan2_kernel(int* __restrict__ bsum, int* __restrict__ off,
                             int NB, int N) {
    __shared__ int s[128];
    int tid = threadIdx.x;
    int v = (tid < NB) ? bsum[tid] : 0;
    s[tid] = v; __syncthreads();
    #pragma unroll
    for (int d = 1; d < 128; d <<= 1) {
        int t = (tid >= d) ? s[tid - d] : 0;
        __syncthreads();
        s[tid] += t;
        __syncthreads();
    }
    if (tid < NB) bsum[tid] = s[tid] - v;    // exclusive
    if (tid == 127) off[N] = s[127];
}

__global__ void scan3_kernel(int* __restrict__ off, const int* __restrict__ bsum, int N) {
    int i = blockIdx.x * blockDim.x + threadIdx.x;
    if (i < N) off[i] += bsum[i >> 10];
}

__global__ void place_kernel(const int* __restrict__ ei, const float* __restrict__ ew,
                             const int* __restrict__ off, int* __restrict__ cursor,
                             int* __restrict__ esrc, float* __restrict__ ewt, int E) {
    int e = blockIdx.x * blockDim.x + threadIdx.x;
    if (e >= E) return;
    int src = __ldg(ei + e);
    int dst = __ldg(ei + E + e);
    int pos = off[dst] + atomicAdd(cursor + dst, 1);
    esrc[pos] = src;
    ewt[pos]  = __ldg(ew + e);
}

// ======================= Aggregation: warp per node ========================
__global__ __launch_bounds__(256)
void gather_kernel(const float* __restrict__ h,
                   const int*   __restrict__ off,
                   const int*   __restrict__ esrc,
                   const float* __restrict__ ewt,
                   float*       __restrict__ agg, int N) {
    int warp = threadIdx.x >> 5, lane = threadIdx.x & 31;
    int node = blockIdx.x * 8 + warp;
    if (node >= N) return;
    int beg = __ldg(off + node), end = __ldg(off + node + 1);

    float4 acc = {0.f, 0.f, 0.f, 0.f};
    int e = beg;
    for (; e + 1 < end; e += 2) {
        int   s0 = __ldg(esrc + e),     s1 = __ldg(esrc + e + 1);
        float w0 = __ldg(ewt + e),      w1 = __ldg(ewt + e + 1);
        float4 v0 = *reinterpret_cast<const float4*>(h + (size_t)s0 * DD + lane * 4);
        float4 v1 = *reinterpret_cast<const float4*>(h + (size_t)s1 * DD + lane * 4);
        acc.x = fmaf(w0, v0.x, fmaf(w1, v1.x, acc.x));
        acc.y = fmaf(w0, v0.y, fmaf(w1, v1.y, acc.y));
        acc.z = fmaf(w0, v0.z, fmaf(w1, v1.z, acc.z));
        acc.w = fmaf(w0, v0.w, fmaf(w1, v1.w, acc.w));
    }
    if (e < end) {
        int   s0 = __ldg(esrc + e);
        float w0 = __ldg(ewt + e);
        float4 v0 = *reinterpret_cast<const float4*>(h + (size_t)s0 * DD + lane * 4);
        acc.x = fmaf(w0, v0.x, acc.x);
        acc.y = fmaf(w0, v0.y, acc.y);
        acc.z = fmaf(w0, v0.z, acc.z);
        acc.w = fmaf(w0, v0.w, acc.w);
    }
    *reinterpret_cast<float4*>(agg + (size_t)node * DD + lane * 4) = acc;
}

// ================= Fused dual-GEMM + bias + LN + PReLU =====================
// 384 threads (12 warps), 8 rows per warp as 4 f32x2 row-pairs.
__global__ __launch_bounds__(384, 1)
void gemm_ln_prelu(const float* __restrict__ hin,
                   const float* __restrict__ agg,
                   const float* __restrict__ Wrel,
                   const float* __restrict__ Wroot,
                   const float* __restrict__ bias,
                   const float* __restrict__ lng,
                   const float* __restrict__ lnb,
                   const float* __restrict__ alpha,
                   float*       __restrict__ hout,
                   int N) {
    extern __shared__ float smem[];
    float4* sWr4 = reinterpret_cast<float4*>(smem);             // 64 KB
    float4* sWo4 = reinterpret_cast<float4*>(smem + 16384);     // 64 KB
    U64*    sP   = reinterpret_cast<U64*>(smem + 32768);        // 96 KB staging

    int tid = threadIdx.x, lane = tid & 31, warp = tid >> 5;

    const float4* Wr4 = reinterpret_cast<const float4*>(Wrel);
    const float4* Wo4 = reinterpret_cast<const float4*>(Wroot);
    for (int i = tid; i < 4096; i += 384) { sWr4[i] = Wr4[i]; sWo4[i] = Wo4[i]; }
    __syncthreads();

    float  al  = __ldg(alpha);
    float4 biv = *reinterpret_cast<const float4*>(bias + lane * 4);
    float4 gg  = *reinterpret_cast<const float4*>(lng  + lane * 4);
    float4 bb  = *reinterpret_cast<const float4*>(lnb  + lane * 4);
    float gA[4] = {gg.x, gg.y, gg.z, gg.w};
    float bA[4] = {bb.x, bb.y, bb.z, bb.w};
    U64 bp[4] = {pk2(biv.x, biv.x), pk2(biv.y, biv.y),
                 pk2(biv.z, biv.z), pk2(biv.w, biv.w)};
    const U64 NEG1   = pk2(-1.f, -1.f);
    const U64 INV128 = pk2(0.0078125f, 0.0078125f);

    U64* sw = sP + warp * 1024;   // 4 pairs x 2 mats x 128 u64
    int gw = blockIdx.x * 12 + warp;
    int stride = gridDim.x * 12 * 8;

    for (int base = gw * 8; base < N; base += stride) {
        __syncwarp();
        #pragma unroll
        for (int p = 0; p < 4; p++) {
            int r0 = base + 2 * p, r1 = r0 + 1;
            float4 a0 = {0,0,0,0}, a1 = {0,0,0,0}, h0 = {0,0,0,0}, h1 = {0,0,0,0};
            if (r0 < N) {
                a0 = *reinterpret_cast<const float4*>(agg + (size_t)r0 * DD + lane * 4);
                h0 = *reinterpret_cast<const float4*>(hin + (size_t)r0 * DD + lane * 4);
            }
            if (r1 < N) {
                a1 = *reinterpret_cast<const float4*>(agg + (size_t)r1 * DD + lane * 4);
                h1 = *reinterpret_cast<const float4*>(hin + (size_t)r1 * DD + lane * 4);
            }
            float2* da = reinterpret_cast<float2*>(sw + (2 * p) * 128);
            float2* dh = reinterpret_cast<float2*>(sw + (2 * p + 1) * 128);
            da[lane * 4 + 0] = make_float2(a0.x, a1.x);
            da[lane * 4 + 1] = make_float2(a0.y, a1.y);
            da[lane * 4 + 2] = make_float2(a0.z, a1.z);
            da[lane * 4 + 3] = make_float2(a0.w, a1.w);
            dh[lane * 4 + 0] = make_float2(h0.x, h1.x);
            dh[lane * 4 + 1] = make_float2(h0.y, h1.y);
            dh[lane * 4 + 2] = make_float2(h0.z, h1.z);
            dh[lane * 4 + 3] = make_float2(h0.w, h1.w);
        }
        __syncwarp();

        U64 acc[4][4];
        #pragma unroll
        for (int p = 0; p < 4; p++)
            #pragma unroll
            for (int c = 0; c < 4; c++) acc[p][c] = bp[c];

        #pragma unroll 4
        for (int k = 0; k < 128; k += 2) {
            float4 wr0 = sWr4[k * 32 + lane],      wr1 = sWr4[k * 32 + 32 + lane];
            float4 wo0 = sWo4[k * 32 + lane],      wo1 = sWo4[k * 32 + 32 + lane];
            U64 wr0p[4] = {pk2(wr0.x,wr0.x), pk2(wr0.y,wr0.y), pk2(wr0.z,wr0.z), pk2(wr0.w,wr0.w)};
            U64 wr1p[4] = {pk2(wr1.x,wr1.x), pk2(wr1.y,wr1.y), pk2(wr1.z,wr1.z), pk2(wr1.w,wr1.w)};
            U64 wo0p[4] = {pk2(wo0.x,wo0.x), pk2(wo0.y,wo0.y), pk2(wo0.z,wo0.z), pk2(wo0.w,wo0.w)};
            U64 wo1p[4] = {pk2(wo1.x,wo1.x), pk2(wo1.y,wo1.y), pk2(wo1.z,wo1.z), pk2(wo1.w,wo1.w)};
            #pragma unroll
            for (int p = 0; p < 4; p++) {
                ulonglong2 ap = *reinterpret_cast<const ulonglong2*>(sw + (2 * p) * 128 + k);
                ulonglong2 hp = *reinterpret_cast<const ulonglong2*>(sw + (2 * p + 1) * 128 + k);
                #pragma unroll
                for (int c = 0; c < 4; c++) {
                    acc[p][c] = f2(ap.x, wr0p[c], acc[p][c]);
                    acc[p][c] = f2(hp.x, wo0p[c], acc[p][c]);
                    acc[p][c] = f2(ap.y, wr1p[c], acc[p][c]);
                    acc[p][c] = f2(hp.y, wo1p[c], acc[p][c]);
                }
            }
        }

        #pragma unroll
        for (int p = 0; p < 4; p++) {
            U64 s = add2(add2(acc[p][0], acc[p][1]), add2(acc[p][2], acc[p][3]));
            #pragma unroll
            for (int o = 16; o; o >>= 1) s = add2(s, shfl64(s, o));
            U64 mu = mul2(s, INV128);
            U64 d[4];
            #pragma unroll
            for (int c = 0; c < 4; c++) d[c] = f2(mu, NEG1, acc[p][c]);
            U64 q = add2(add2(mul2(d[0], d[0]), mul2(d[1], d[1])),
                         add2(mul2(d[2], d[2]), mul2(d[3], d[3])));
            #pragma unroll
            for (int o = 16; o; o >>= 1) q = add2(q, shfl64(q, o));
            float ql, qh; upk2(q, ql, qh);
            float rl = rsqrtf(ql * 0.0078125f + 1e-5f);
            float rh = rsqrtf(qh * 0.0078125f + 1e-5f);

            int r0 = base + 2 * p, r1 = r0 + 1;
            float y0[4], y1[4];
            #pragma unroll
            for (int c = 0; c < 4; c++) {
                float dl, dh2; upk2(d[c], dl, dh2);
                float v0 = dl * rl * gA[c] + bA[c];
                float v1 = dh2 * rh * gA[c] + bA[c];
                y0[c] = v0 >= 0.f ? v0 : al * v0;
                y1[c] = v1 >= 0.f ? v1 : al * v1;
            }
            if (r0 < N)
                *reinterpret_cast<float4*>(hout + (size_t)r0 * DD + lane * 4) =
                    make_float4(y0[0], y0[1], y0[2], y0[3]);
            if (r1 < N)
                *reinterpret_cast<float4*>(hout + (size_t)r1 * DD + lane * 4) =
                    make_float4(y1[0], y1[1], y1[2], y1[3]);
        }
    }
}

// ======================= Classifier ========================================
__global__ __launch_bounds__(256, 2)
void classifier_kernel(const float* __restrict__ hin,
                       const float* __restrict__ W1,
                       const float* __restrict__ b1,
                       const float* __restrict__ lng,
                       const float* __restrict__ lnb,
                       const float* __restrict__ W2,
                       const float* __restrict__ b2,
                       float*       __restrict__ out,
                       int N) {
    extern __shared__ float smem[];
    float4* sW4 = reinterpret_cast<float4*>(smem);          // 64 KB
    U64*    sP  = reinterpret_cast<U64*>(smem + 16384);     // 32 KB staging

    int tid = threadIdx.x, lane = tid & 31, warp = tid >> 5;

    const float4* W14 = reinterpret_cast<const float4*>(W1);
    #pragma unroll
    for (int i = tid; i < 4096; i += 256) sW4[i] = W14[i];
    __syncthreads();

    float4 b1v = *reinterpret_cast<const float4*>(b1  + lane * 4);
    float4 gg  = *reinterpret_cast<const float4*>(lng + lane * 4);
    float4 bb  = *reinterpret_cast<const float4*>(lnb + lane * 4);
    float gA[4] = {gg.x, gg.y, gg.z, gg.w};
    float bA[4] = {bb.x, bb.y, bb.z, bb.w};
    U64 bp[4] = {pk2(b1v.x, b1v.x), pk2(b1v.y, b1v.y),
                 pk2(b1v.z, b1v.z), pk2(b1v.w, b1v.w)};
    const U64 NEG1   = pk2(-1.f, -1.f);
    const U64 INV128 = pk2(0.0078125f, 0.0078125f);

    float w2c0[4], w2c1[4];
    #pragma unroll
    for (int c = 0; c < 4; c++) {
        w2c0[c] = __ldg(W2 + (lane * 4 + c) * 2 + 0);
        w2c1[c] = __ldg(W2 + (lane * 4 + c) * 2 + 1);
    }
    float b20 = __ldg(b2 + 0), b21 = __ldg(b2 + 1);

    U64* sw = sP + warp * 512;
    int gw = blockIdx.x * 8 + warp;
    int stride = gridDim.x * 8 * 8;

    for (int base = gw * 8; base < N; base += stride) {
        __syncwarp();
        #pragma unroll
        for (int p = 0; p < 4; p++) {
            int r0 = base + 2 * p, r1 = r0 + 1;
            float4 x0 = {0,0,0,0}, x1 = {0,0,0,0};
            if (r0 < N) x0 = *reinterpret_cast<const float4*>(hin + (size_t)r0 * DD + lane * 4);
            if (r1 < N) x1 = *reinterpret_cast<const float4*>(hin + (size_t)r1 * DD + lane * 4);
            float2* dx = reinterpret_cast<float2*>(sw + p * 128);
            dx[lane * 4 + 0] = make_float2(x0.x, x1.x);
            dx[lane * 4 + 1] = make_float2(x0.y, x1.y);
            dx[lane * 4 + 2] = make_float2(x0.z, x1.z);
            dx[lane * 4 + 3] = make_float2(x0.w, x1.w);
        }
        __syncwarp();

        U64 acc[4][4];
        #pragma unroll
        for (int p = 0; p < 4; p++)
            #pragma unroll
            for (int c = 0; c < 4; c++) acc[p][c] = bp[c];

        #pragma unroll 4
        for (int k = 0; k < 128; k += 2) {
            float4 w0 = sW4[k * 32 + lane], w1 = sW4[k * 32 + 32 + lane];
            U64 w0p[4] = {pk2(w0.x,w0.x), pk2(w0.y,w0.y), pk2(w0.z,w0.z), pk2(w0.w,w0.w)};
            U64 w1p[4] = {pk2(w1.x,w1.x), pk2(w1.y,w1.y), pk2(w1.z,w1.z), pk2(w1.w,w1.w)};
            #pragma unroll
            for (int p = 0; p < 4; p++) {
                ulonglong2 xp = *reinterpret_cast<const ulonglong2*>(sw + p * 128 + k);
                #pragma unroll
                for (int c = 0; c < 4; c++) {
                    acc[p][c] = f2(xp.x, w0p[c], acc[p][c]);
                    acc[p][c] = f2(xp.y, w1p[c], acc[p][c]);
                }
            }
        }

        #pragma unroll
        for (int p = 0; p < 4; p++) {
            #pragma unroll
            for (int c = 0; c < 4; c++) {
                float lo, hi; upk2(acc[p][c], lo, hi);
                acc[p][c] = pk2(fmaxf(lo, 0.f), fmaxf(hi, 0.f));
            }
            U64 s = add2(add2(acc[p][0], acc[p][1]), add2(acc[p][2], acc[p][3]));
            #pragma unroll
            for (int o = 16; o; o >>= 1) s = add2(s, shfl64(s, o));
            U64 mu = mul2(s, INV128);
            U64 d[4];
            #pragma unroll
            for (int c = 0; c < 4; c++) d[c] = f2(mu, NEG1, acc[p][c]);
            U64 q = add2(add2(mul2(d[0], d[0]), mul2(d[1], d[1])),
                         add2(mul2(d[2], d[2]), mul2(d[3], d[3])));
            #pragma unroll
            for (int o = 16; o; o >>= 1) q = add2(q, shfl64(q, o));
            float ql, qh; upk2(q, ql, qh);
            float rl = rsqrtf(ql * 0.0078125f + 1e-5f);
            float rh = rsqrtf(qh * 0.0078125f + 1e-5f);

            float p0lo = 0.f, p1lo = 0.f, p0hi = 0.f, p1hi = 0.f;
            #pragma unroll
            for (int c = 0; c < 4; c++) {
                float dl, dh2; upk2(d[c], dl, dh2);
                float zl = dl * rl * gA[c] + bA[c];
                float zh = dh2 * rh * gA[c] + bA[c];
                p0lo += zl * w2c0[c]; p1lo += zl * w2c1[c];
                p0hi += zh * w2c0[c]; p1hi += zh * w2c1[c];
            }
            U64 P0 = pk2(p0lo, p0hi), P1 = pk2(p1lo, p1hi);
            #pragma unroll
            for (int o = 16; o; o >>= 1) {
                P0 = add2(P0, shfl64(P0, o));
                P1 = add2(P1, shfl64(P1, o));
            }
            if (lane == 0) {
                float a0, a1, c0, c1;
                upk2(P0, a0, a1); upk2(P1, c0, c1);
                int r0 = base + 2 * p, r1 = r0 + 1;
                if (r0 < N) { out[(size_t)r0 * 2 + 0] = a0 + b20; out[(size_t)r0 * 2 + 1] = c0 + b21; }
                if (r1 < N) { out[(size_t)r1 * 2 + 0] = a1 + b20; out[(size_t)r1 * 2 + 1] = c1 + b21; }
            }
        }
    }
}

// ---------------------------------------------------------------------------
extern "C" void kernel_launch(void* const* d_in, const int* in_sizes, int n_in,
                              void* d_out, int out_size) {
    const float* features = (const float*)d_in[0];
    const int*   ei       = (const int*)  d_in[1];
    const float* ew       = (const float*)d_in[2];
    const float* Wrel     = (const float*)d_in[3];
    const float* Wroot    = (const float*)d_in[4];
    const float* bias     = (const float*)d_in[5];
    const float* lng      = (const float*)d_in[6];
    const float* lnb      = (const float*)d_in[7];
    const float* alpha    = (const float*)d_in[8];
    const float* W1       = (const float*)d_in[9];
    const float* b1       = (const float*)d_in[10];
    const float* cg       = (const float*)d_in[11];
    const float* cb       = (const float*)d_in[12];
    const float* W2       = (const float*)d_in[13];
    const float* b2       = (const float*)d_in[14];

    int N = in_sizes[0] / DD;
    int E = in_sizes[1] / 2;
    int L = in_sizes[8];

    float *buf0, *buf1, *agg, *ewt;
    int *cnt, *off, *bsum, *esrc;
    cudaGetSymbolAddress((void**)&buf0, g_buf0);
    cudaGetSymbolAddress((void**)&buf1, g_buf1);
    cudaGetSymbolAddress((void**)&agg,  g_agg);
    cudaGetSymbolAddress((void**)&cnt,  g_cnt);
    cudaGetSymbolAddress((void**)&off,  g_off);
    cudaGetSymbolAddress((void**)&bsum, g_bsum);
    cudaGetSymbolAddress((void**)&esrc, g_esrc);
    cudaGetSymbolAddress((void**)&ewt,  g_ewt);

    int sm = 148;
    cudaDeviceGetAttribute(&sm, cudaDevAttrMultiProcessorCount, 0);

    size_t smemG = 229376;  // 128 KB weights + 96 KB staging
    size_t smemC = 98304;   // 64 KB + 32 KB
    cudaFuncSetAttribute(gemm_ln_prelu,     cudaFuncAttributeMaxDynamicSharedMemorySize, (int)smemG);
    cudaFuncSetAttribute(classifier_kernel, cudaFuncAttributeMaxDynamicSharedMemorySize, (int)smemC);

    // ---- CSR build (reused across all layers) ----
    int NB = (N + 1023) / 1024;
    cudaMemsetAsync(cnt, 0, (size_t)N * sizeof(int));
    hist_kernel <<<(E + 255) / 256, 256>>>(ei, cnt, E);
    scan1_kernel<<<NB, 1024>>>(cnt, off, bsum, N);
    scan2_kernel<<<1, 128>>>(bsum, off, NB, N);
    scan3_kernel<<<(N + 255) / 256, 256>>>(off, bsum, N);
    cudaMemsetAsync(cnt, 0, (size_t)N * sizeof(int));   // cursor
    place_kernel<<<(E + 255) / 256, 256>>>(ei, ew, off, cnt, esrc, ewt, E);

    int gatherBlocks = (N + 7) / 8;

    const float* hin = features;
    float* pong[2] = { buf0, buf1 };
    for (int i = 0; i < L; i++) {
        float* hout = pong[i & 1];
        gather_kernel<<<gatherBlocks, 256>>>(hin, off, esrc, ewt, agg, N);
        gemm_ln_prelu<<<sm, 384, smemG>>>(hin, agg,
                                          Wrel  + (size_t)i * DD * DD,
                                          Wroot + (size_t)i * DD * DD,
                                          bias + i * DD, lng + i * DD, lnb + i * DD,
                                          alpha + i, hout, N);
        hin = hout;
    }
    classifier_kernel<<<2 * sm, 256, smemC>>>(hin, W1, b1, cg, cb, W2, b2,
                                              (float*)d_out, N);
}